// round 13
// baseline (speedup 1.0000x reference)
#include <cuda_runtime.h>
#include <cuda_fp16.h>
#include <cstdint>

#define Bb 4
#define Ss 2048
#define Ee 1024
#define Hh 16
#define Dd 64
#define STRD 72   // fp16 smem row stride: 144B = 9*16B -> conflict-free ldmatrix phases

// fp16 copies of inputs (prep kernel), packed fp16x2 words
__device__ uint32_t g_Xq[(size_t)Bb * Ss * Ee / 2];
__device__ uint32_t g_Xh[(size_t)Bb * Ss * Ee / 2];
__device__ uint32_t g_Wq16[(size_t)Hh * Dd * Ee / 2];
__device__ uint32_t g_Wk16[(size_t)Hh * Dd * Ee / 2];
__device__ uint32_t g_Wv16[(size_t)Hh * Dd * Ee / 2];
// bit-packed mask: word w covers cols [w*64, w*64+64) of one (b, s) row
__device__ unsigned long long g_pm64[(size_t)Bb * Ss * Ss / 64];
// projected Q/K/V, fp16 packed, (B,H,S,D)
#define NWORDS (size_t)(Bb * Hh * Ss * Dd / 2)
__device__ uint32_t g_Qh[NWORDS];
__device__ uint32_t g_Kh[NWORDS];
__device__ uint32_t g_Vh[NWORDS];

// ---------------- helpers ----------------
__device__ __forceinline__ uint32_t pack_f16x2(float lo, float hi) {
    __half2 h = __floats2half2_rn(lo, hi);
    return *(uint32_t*)&h;
}
__device__ __forceinline__ float ex2f(float x) {
    float r; asm("ex2.approx.f32 %0, %1;" : "=f"(r) : "f"(x)); return r;
}
__device__ __forceinline__ uint32_t ex2h2(uint32_t x) {
    uint32_t r; asm("ex2.approx.f16x2 %0, %1;" : "=r"(r) : "r"(x)); return r;
}
__device__ __forceinline__ uint32_t hmin2u(uint32_t a, uint32_t b) {
    __half2 r = __hmin2(*(__half2*)&a, *(__half2*)&b);
    return *(uint32_t*)&r;
}
__device__ __forceinline__ uint32_t hmax2u(uint32_t a, uint32_t b) {
    __half2 r = __hmax2(*(__half2*)&a, *(__half2*)&b);
    return *(uint32_t*)&r;
}
__device__ __forceinline__ uint32_t hfma2u(uint32_t a, uint32_t b, uint32_t c) {
    __half2 r = __hfma2(*(__half2*)&a, *(__half2*)&b, *(__half2*)&c);
    return *(uint32_t*)&r;
}
// f32-accum fp16 MMA
__device__ __forceinline__ void mma16816(float c[4], const uint32_t a[4], uint32_t b0, uint32_t b1) {
    asm volatile(
        "mma.sync.aligned.m16n8k16.row.col.f32.f16.f16.f32 "
        "{%0,%1,%2,%3},{%4,%5,%6,%7},{%8,%9},{%0,%1,%2,%3};\n"
        : "+f"(c[0]), "+f"(c[1]), "+f"(c[2]), "+f"(c[3])
        : "r"(a[0]), "r"(a[1]), "r"(a[2]), "r"(a[3]), "r"(b0), "r"(b1));
}
// f16-accum fp16 MMA (full rate)
__device__ __forceinline__ void mma16816h(uint32_t c[2], const uint32_t a[4], uint32_t b0, uint32_t b1) {
    asm volatile(
        "mma.sync.aligned.m16n8k16.row.col.f16.f16.f16.f16 "
        "{%0,%1},{%2,%3,%4,%5},{%6,%7},{%0,%1};\n"
        : "+r"(c[0]), "+r"(c[1])
        : "r"(a[0]), "r"(a[1]), "r"(a[2]), "r"(a[3]), "r"(b0), "r"(b1));
}
__device__ __forceinline__ void ldmA(const unsigned short* t, int row0, int k0, uint32_t r[4]) {
    int lane = threadIdx.x & 31;
    int rr = row0 + (lane & 7) + 8 * ((lane >> 3) & 1);
    int cc = k0 + 8 * (lane >> 4);
    uint32_t a = (uint32_t)__cvta_generic_to_shared(t + rr * STRD + cc);
    asm volatile("ldmatrix.sync.aligned.m8n8.x4.shared.b16 {%0,%1,%2,%3},[%4];"
                 : "=r"(r[0]), "=r"(r[1]), "=r"(r[2]), "=r"(r[3]) : "r"(a));
}
__device__ __forceinline__ void ldmB(const unsigned short* t, int n0, int k0, uint32_t r[4]) {
    int lane = threadIdx.x & 31;
    int rr = n0 + (lane & 7) + 8 * (lane >> 4);
    int cc = k0 + 8 * ((lane >> 3) & 1);
    uint32_t a = (uint32_t)__cvta_generic_to_shared(t + rr * STRD + cc);
    asm volatile("ldmatrix.sync.aligned.m8n8.x4.shared.b16 {%0,%1,%2,%3},[%4];"
                 : "=r"(r[0]), "=r"(r[1]), "=r"(r[2]), "=r"(r[3]) : "r"(a));
}
__device__ __forceinline__ void ldmBT(const unsigned short* t, int kk0, int d0, uint32_t r[4]) {
    int lane = threadIdx.x & 31;
    int rr = kk0 + (lane & 7) + 8 * ((lane >> 3) & 1);
    int cc = d0 + 8 * (lane >> 4);
    uint32_t a = (uint32_t)__cvta_generic_to_shared(t + rr * STRD + cc);
    asm volatile("ldmatrix.sync.aligned.m8n8.x4.trans.shared.b16 {%0,%1,%2,%3},[%4];"
                 : "=r"(r[0]), "=r"(r[1]), "=r"(r[2]), "=r"(r[3]) : "r"(a));
}
__device__ __forceinline__ void cp16(void* smem_dst, const void* gsrc) {
    uint32_t s = (uint32_t)__cvta_generic_to_shared(smem_dst);
    asm volatile("cp.async.ca.shared.global [%0], [%1], 16;" :: "r"(s), "l"(gsrc));
}

// ---------------------------------------------------------------------------
// Prep: fp32 -> fp16 packed copies of q, hx, Wq, Wk, Wv (conversions only;
// mask packing now overlaps with proj as its 4th grid-z slice).
// ---------------------------------------------------------------------------
__global__ __launch_bounds__(256) void prep_f16(const float* __restrict__ q,
                                                const float* __restrict__ hx,
                                                const float* __restrict__ Wq,
                                                const float* __restrict__ Wk,
                                                const float* __restrict__ Wv) {
    const int z = blockIdx.y;
    const float* src = (z == 0) ? q : (z == 1) ? hx : (z == 2) ? Wq : (z == 3) ? Wk : Wv;
    uint32_t* dst = (z == 0) ? g_Xq : (z == 1) ? g_Xh : (z == 2) ? g_Wq16 : (z == 3) ? g_Wk16 : g_Wv16;
    size_t n = (z < 2) ? ((size_t)Bb * Ss * Ee / 2) : ((size_t)Hh * Dd * Ee / 2);
    size_t stride = (size_t)gridDim.x * blockDim.x;
    for (size_t i = (size_t)blockIdx.x * blockDim.x + threadIdx.x; i < n; i += stride) {
        float2 v = ((const float2*)src)[i];
        dst[i] = pack_f16x2(v.x, v.y);
    }
}

// ---------------------------------------------------------------------------
// Projections: C = X @ W^T (fp16 in, fp16 packed out, (B,H,S,D)).
// BM=128, BN=128, BK=64. 128 threads, 4 warps as 2(m64) x 2(n64).
// 2-stage cp.async, single barrier per chunk. 2 CTAs/SM (round-11 proven).
// Grid z==3 slice packs the mask bitmask (DRAM-bound; overlaps proj tail).
// ---------------------------------------------------------------------------
__global__ __launch_bounds__(128, 2) void proj_kernel(const int* __restrict__ mask) {
    const int tid = threadIdx.x;
    const int wid = tid >> 5, lane = tid & 31;

    if (blockIdx.z == 3) {
        // mask (int32, nonzero = disallowed) -> bitmask, 64 cols per uint64
        size_t gwid = ((size_t)(blockIdx.y * gridDim.x + blockIdx.x) * 4 + wid);
        size_t nwarps = (size_t)gridDim.x * gridDim.y * 4;
        const size_t NW = (size_t)Bb * Ss * Ss / 64;
        for (size_t w = gwid; w < NW; w += nwarps) {
            const int* p = mask + w * 64;
            uint32_t b0 = __ballot_sync(0xffffffffu, p[lane] != 0);
            uint32_t b1 = __ballot_sync(0xffffffffu, p[lane + 32] != 0);
            if (lane == 0)
                g_pm64[w] = (unsigned long long)b0 | ((unsigned long long)b1 << 32);
        }
        return;
    }

    extern __shared__ unsigned short sm16[];
    const int z = blockIdx.z;
    const uint32_t* X = (z == 0) ? g_Xq : g_Xh;
    const uint32_t* W = (z == 0) ? g_Wq16 : (z == 1) ? g_Wk16 : g_Wv16;
    uint32_t* dst = (z == 0) ? g_Qh : (z == 1) ? g_Kh : g_Vh;

    const int g = lane >> 2, t4 = lane & 3;
    const int wm = wid >> 1, wn = wid & 1;
    const int mbase = blockIdx.y * 128;
    const int nbase = blockIdx.x * 128;

#define PSTAGE(st) (sm16 + (st) * 256 * STRD)
#define PROJ_ISSUE(et, st)                                                        \
    {                                                                             \
        unsigned short* xs_ = PSTAGE(st);                                         \
        unsigned short* ws_ = PSTAGE(st) + 128 * STRD;                            \
        int ew_ = (et) * 32; /* word offset of e-chunk */                         \
        _Pragma("unroll")                                                         \
        for (int i_ = 0; i_ < 16; i_++) {                                         \
            int slot_ = i_ * 128 + tid;                                           \
            if (slot_ < 1024) {                                                   \
                int r_ = slot_ >> 3, c_ = slot_ & 7;                              \
                cp16(xs_ + r_ * STRD + c_ * 8,                                    \
                     X + (size_t)(mbase + r_) * 512 + ew_ + c_ * 4);              \
            } else {                                                              \
                int s2_ = slot_ - 1024;                                           \
                int r_ = s2_ >> 3, c_ = s2_ & 7;                                  \
                cp16(ws_ + r_ * STRD + c_ * 8,                                    \
                     W + (size_t)(nbase + r_) * 512 + ew_ + c_ * 4);              \
            }                                                                     \
        }                                                                         \
        asm volatile("cp.async.commit_group;");                                   \
    }

    float c[4][8][4] = {};
    PROJ_ISSUE(0, 0);
    asm volatile("cp.async.wait_group 0;");
    __syncthreads();                          // stage 0 ready, all warps present

    for (int et = 0; et < 16; et++) {
        if (et + 1 < 16) PROJ_ISSUE(et + 1, (et + 1) & 1);

        const unsigned short* Xs = PSTAGE(et & 1);
        const unsigned short* Ws = PSTAGE(et & 1) + 128 * STRD;

#pragma unroll
        for (int ks = 0; ks < 4; ks++) {
            uint32_t ax[4][4], bw[4][4];
#pragma unroll
            for (int mt = 0; mt < 4; mt++) ldmA(Xs, wm * 64 + mt * 16, ks * 16, ax[mt]);
#pragma unroll
            for (int nt2 = 0; nt2 < 4; nt2++) ldmB(Ws, wn * 64 + nt2 * 16, ks * 16, bw[nt2]);
#pragma unroll
            for (int mt = 0; mt < 4; mt++)
#pragma unroll
                for (int nt2 = 0; nt2 < 4; nt2++) {
                    mma16816(c[mt][2 * nt2],     ax[mt], bw[nt2][0], bw[nt2][1]);
                    mma16816(c[mt][2 * nt2 + 1], ax[mt], bw[nt2][2], bw[nt2][3]);
                }
        }

        if (et + 1 < 16) {
            asm volatile("cp.async.wait_group 0;");
            __syncthreads();
        }
    }

    // epilogue: each warp's n64 block == one head
    const int h = blockIdx.x * 2 + wn;
#pragma unroll
    for (int mt = 0; mt < 4; mt++) {
        int m0 = mbase + wm * 64 + mt * 16 + g;
        int b = m0 >> 11, s0 = m0 & 2047;
        size_t base0 = (((size_t)b * Hh + h) * Ss + s0) * (Dd / 2);
        size_t base1 = base0 + 8 * (Dd / 2);
#pragma unroll
        for (int nt = 0; nt < 8; nt++) {
            int dw = nt * 4 + t4;   // d/2
            dst[base0 + dw] = pack_f16x2(c[mt][nt][0], c[mt][nt][1]);
            dst[base1 + dw] = pack_f16x2(c[mt][nt][2], c[mt][nt][3]);
        }
    }
}

// ---------------------------------------------------------------------------
// Flash attention. CTA = 128 q-rows x (h, b); 4 warps, warp owns 32 q-rows.
// QK^T in f16 accumulators; mask = hmin2 vs ±inf; exp fused f16x2;
// l via ones-MMA with CONSTANT B-fragment (ones region reads as 0x3C003C00 —
// no LDSM, no pad init); 4-stage cp.async, single barrier; rescale-skip vote;
// pairwise-packed hmax2 shuffle reduction; persistent nm2 exp-bias.
// ---------------------------------------------------------------------------
#define SCLOG2 0.18033688011112042f  // 0.125 * log2(e)
#define MRINIT -30.0f
#define NKT (Ss / 64)                 // 32 k-tiles
#define ASTAGE(st) (sm16 + (st) * 128 * STRD)   // K at +0 (64 rows), V at +64*STRD

__global__ __launch_bounds__(128, 2) void attn_kernel(float* __restrict__ out) {
    extern __shared__ unsigned short sm16[];

    const int qt = blockIdx.x, h = blockIdx.y, b = blockIdx.z;
    const int tid = threadIdx.x;
    const int wid = tid >> 5, lane = tid & 31;
    const int g = lane >> 2, t4 = lane & 3;

    const size_t bh_base = ((size_t)b * Hh + h) * Ss;
    const uint32_t* Kg = g_Kh + bh_base * (Dd / 2);
    const uint32_t* Vg = g_Vh + bh_base * (Dd / 2);

    {
        const uint32_t* Qg = g_Qh + (bh_base + qt * 128) * (Dd / 2);
#pragma unroll
        for (int i = 0; i < 8; i++) {
            int slot = i * 128 + tid;
            int r = slot >> 3, c = slot & 7;
            *(int4*)(sm16 + r * STRD + c * 8) = *(const int4*)&Qg[r * 32 + c * 4];
        }
    }
    __syncthreads();
    uint32_t aq[2][4][4];
#pragma unroll
    for (int mh = 0; mh < 2; mh++)
#pragma unroll
        for (int ks = 0; ks < 4; ks++)
            ldmA(sm16, wid * 32 + mh * 16, ks * 16, aq[mh][ks]);
    __syncthreads();   // everyone done reading Q before pipeline overwrites

#define ATTN_ISSUE(kt, st)                                                        \
    {                                                                             \
        const uint32_t* ks_ = Kg + (size_t)(kt) * 64 * 32;                        \
        const uint32_t* vs_ = Vg + (size_t)(kt) * 64 * 32;                        \
        unsigned short* kb_ = ASTAGE(st);                                         \
        unsigned short* vb_ = ASTAGE(st) + 64 * STRD;                             \
        _Pragma("unroll")                                                         \
        for (int i_ = 0; i_ < 8; i_++) {                                          \
            int slot_ = i_ * 128 + tid;                                           \
            int r_ = (slot_ >> 3) & 63, c_ = slot_ & 7;                           \
            if (slot_ < 512) cp16(kb_ + r_ * STRD + c_ * 8, ks_ + r_ * 32 + c_ * 4); \
            else             cp16(vb_ + r_ * STRD + c_ * 8, vs_ + r_ * 32 + c_ * 4); \
        }                                                                         \
        asm volatile("cp.async.commit_group;");                                   \
    }

    ATTN_ISSUE(0, 0);
    ATTN_ISSUE(1, 1);
    ATTN_ISSUE(2, 2);

    float o[2][8][4] = {};
    float lacc[2][4] = {};
    float mr[4] = {MRINIT, MRINIT, MRINIT, MRINIT};
    uint32_t nm2[4];
#pragma unroll
    for (int rgi = 0; rgi < 4; rgi++)
        nm2[rgi] = pack_f16x2(-MRINIT * SCLOG2, -MRINIT * SCLOG2);

    const int r0 = qt * 128 + wid * 32 + g;
    const unsigned long long* pmr = g_pm64 + ((size_t)b * Ss + r0) * (Ss / 64);

    for (int kt = 0; kt < NKT; kt++) {
        unsigned long long mA = pmr[kt];
        unsigned long long mB = pmr[kt + 8 * (Ss / 64)];
        unsigned long long mC = pmr[kt + 16 * (Ss / 64)];
        unsigned long long mD = pmr[kt + 24 * (Ss / 64)];

        asm volatile("cp.async.wait_group 2;");
        __syncthreads();
        if (kt + 3 < NKT) { ATTN_ISSUE(kt + 3, (kt + 3) & 3); }
        else { asm volatile("cp.async.commit_group;"); }

        const unsigned short* Kt = ASTAGE(kt & 3);
        const unsigned short* Vt = ASTAGE(kt & 3) + 64 * STRD;

        uint32_t s2[2][8][2];
#pragma unroll
        for (int mh = 0; mh < 2; mh++)
#pragma unroll
            for (int nt = 0; nt < 8; nt++) { s2[mh][nt][0] = 0u; s2[mh][nt][1] = 0u; }
#pragma unroll
        for (int ks = 0; ks < 4; ks++) {
            uint32_t bk[4][4];
#pragma unroll
            for (int nt2 = 0; nt2 < 4; nt2++) ldmB(Kt, nt2 * 16, ks * 16, bk[nt2]);
#pragma unroll
            for (int mh = 0; mh < 2; mh++)
#pragma unroll
                for (int nt2 = 0; nt2 < 4; nt2++) {
                    mma16816h(s2[mh][2 * nt2],     aq[mh][ks], bk[nt2][0], bk[nt2][1]);
                    mma16816h(s2[mh][2 * nt2 + 1], aq[mh][ks], bk[nt2][2], bk[nt2][3]);
                }
        }

#pragma unroll
        for (int nt = 0; nt < 8; nt++) {
            int sh = nt * 8 + 2 * t4;
            uint32_t a2 = (uint32_t)(mA >> sh) & 3u;
            uint32_t b2 = (uint32_t)(mB >> sh) & 3u;
            uint32_t c2 = (uint32_t)(mC >> sh) & 3u;
            uint32_t d2 = (uint32_t)(mD >> sh) & 3u;
            s2[0][nt][0] = hmin2u(s2[0][nt][0], 0x7C007C00u | ((a2 & 1) << 15) | ((a2 & 2) << 30));
            s2[0][nt][1] = hmin2u(s2[0][nt][1], 0x7C007C00u | ((b2 & 1) << 15) | ((b2 & 2) << 30));
            s2[1][nt][0] = hmin2u(s2[1][nt][0], 0x7C007C00u | ((c2 & 1) << 15) | ((c2 & 2) << 30));
            s2[1][nt][1] = hmin2u(s2[1][nt][1], 0x7C007C00u | ((d2 & 1) << 15) | ((d2 & 2) << 30));
        }

        // ---- row max: hmax2 tree, then pairwise-packed quad reduction ----
        uint32_t m2[4] = {0xFC00FC00u, 0xFC00FC00u, 0xFC00FC00u, 0xFC00FC00u};
#pragma unroll
        for (int nt = 0; nt < 8; nt++) {
            m2[0] = hmax2u(m2[0], s2[0][nt][0]);
            m2[1] = hmax2u(m2[1], s2[0][nt][1]);
            m2[2] = hmax2u(m2[2], s2[1][nt][0]);
            m2[3] = hmax2u(m2[3], s2[1][nt][1]);
        }
        __half2 h01 = __halves2half2(
            __hmax(__low2half(*(__half2*)&m2[0]), __high2half(*(__half2*)&m2[0])),
            __hmax(__low2half(*(__half2*)&m2[1]), __high2half(*(__half2*)&m2[1])));
        __half2 h23 = __halves2half2(
            __hmax(__low2half(*(__half2*)&m2[2]), __high2half(*(__half2*)&m2[2])),
            __hmax(__low2half(*(__half2*)&m2[3]), __high2half(*(__half2*)&m2[3])));
        uint32_t p01 = *(uint32_t*)&h01, p23 = *(uint32_t*)&h23;
        p01 = hmax2u(p01, __shfl_xor_sync(0xffffffffu, p01, 1));
        p01 = hmax2u(p01, __shfl_xor_sync(0xffffffffu, p01, 2));
        p23 = hmax2u(p23, __shfl_xor_sync(0xffffffffu, p23, 1));
        p23 = hmax2u(p23, __shfl_xor_sync(0xffffffffu, p23, 2));
        float2 f01 = __half22float2(*(__half2*)&p01);
        float2 f23 = __half22float2(*(__half2*)&p23);
        float mn[4];
        mn[0] = fmaxf(mr[0], f01.x);
        mn[1] = fmaxf(mr[1], f01.y);
        mn[2] = fmaxf(mr[2], f23.x);
        mn[3] = fmaxf(mr[3], f23.y);
        bool same = (mn[0] == mr[0]) && (mn[1] == mr[1]) &&
                    (mn[2] == mr[2]) && (mn[3] == mr[3]);
        if (!__all_sync(0xffffffffu, same)) {
            float corr[4];
#pragma unroll
            for (int rgi = 0; rgi < 4; rgi++) {
                corr[rgi] = ex2f((mr[rgi] - mn[rgi]) * SCLOG2);
                mr[rgi] = mn[rgi];
                float nmv = -mr[rgi] * SCLOG2;
                nm2[rgi] = pack_f16x2(nmv, nmv);
            }
#pragma unroll
            for (int nd = 0; nd < 8; nd++) {
                o[0][nd][0] *= corr[0]; o[0][nd][1] *= corr[0];
                o[0][nd][2] *= corr[1]; o[0][nd][3] *= corr[1];
                o[1][nd][0] *= corr[2]; o[1][nd][1] *= corr[2];
                o[1][nd][2] *= corr[3]; o[1][nd][3] *= corr[3];
            }
            lacc[0][0] *= corr[0]; lacc[0][1] *= corr[0];
            lacc[0][2] *= corr[1]; lacc[0][3] *= corr[1];
            lacc[1][0] *= corr[2]; lacc[1][1] *= corr[2];
            lacc[1][2] *= corr[3]; lacc[1][3] *= corr[3];
        }

        const uint32_t sc2 = 0x31C631C6u;   // half2(0.18033688)
#pragma unroll
        for (int mh = 0; mh < 2; mh++)
#pragma unroll
            for (int nt = 0; nt < 8; nt++) {
                s2[mh][nt][0] = ex2h2(hfma2u(s2[mh][nt][0], sc2, nm2[2 * mh]));
                s2[mh][nt][1] = ex2h2(hfma2u(s2[mh][nt][1], sc2, nm2[2 * mh + 1]));
            }

        // ---- O += P V ; l += P @ ones (constant ones B-fragment) ----
        const uint32_t ONE2 = 0x3C003C00u;  // ldmatrix of an all-ones region
#pragma unroll
        for (int ks2 = 0; ks2 < 4; ks2++) {
            uint32_t bv[4][4];
#pragma unroll
            for (int d2 = 0; d2 < 4; d2++) ldmBT(Vt, ks2 * 16, d2 * 16, bv[d2]);
#pragma unroll
            for (int mh = 0; mh < 2; mh++) {
                const uint32_t pa[4] = {s2[mh][2 * ks2][0], s2[mh][2 * ks2][1],
                                        s2[mh][2 * ks2 + 1][0], s2[mh][2 * ks2 + 1][1]};
#pragma unroll
                for (int d2 = 0; d2 < 4; d2++) {
                    mma16816(o[mh][2 * d2],     pa, bv[d2][0], bv[d2][1]);
                    mma16816(o[mh][2 * d2 + 1], pa, bv[d2][2], bv[d2][3]);
                }
                mma16816(lacc[mh], pa, ONE2, ONE2);
            }
        }
    }

#pragma unroll
    for (int mh = 0; mh < 2; mh++) {
        float invA = 1.f / fmaxf(lacc[mh][0], 1e-30f);
        float invB = 1.f / fmaxf(lacc[mh][2], 1e-30f);
        int rA = r0 + 16 * mh, rB = rA + 8;
        float* oA = out + ((size_t)b * Ss + rA) * (Hh * Dd) + h * Dd;
        float* oB = out + ((size_t)b * Ss + rB) * (Hh * Dd) + h * Dd;
#pragma unroll
        for (int nd = 0; nd < 8; nd++) {
            int d = nd * 8 + 2 * t4;
            *(float2*)&oA[d] = make_float2(o[mh][nd][0] * invA, o[mh][nd][1] * invA);
            *(float2*)&oB[d] = make_float2(o[mh][nd][2] * invB, o[mh][nd][3] * invB);
        }
    }
}

// ---------------------------------------------------------------------------
extern "C" void kernel_launch(void* const* d_in, const int* in_sizes, int n_in,
                              void* d_out, int out_size) {
    const float* q  = (const float*)d_in[0];
    const float* hx = (const float*)d_in[1];
    const int* mask = (const int*)d_in[2];
    const float* Wq = (const float*)d_in[3];
    const float* Wk = (const float*)d_in[4];
    const float* Wv = (const float*)d_in[5];
    float* out = (float*)d_out;

    prep_f16<<<dim3(2048, 5), 256>>>(q, hx, Wq, Wk, Wv);

    const int psmem = 2 * 256 * STRD * 2;   // 73728 B (2 stages)
    cudaFuncSetAttribute(proj_kernel, cudaFuncAttributeMaxDynamicSharedMemorySize, psmem);
    // z = 0..2: Q/K/V projections; z = 3: mask bit-packing (overlapped)
    proj_kernel<<<dim3(Hh * Dd / 128, Bb * Ss / 128, 4), 128, psmem>>>(mask);

    const int asmem = 4 * 128 * STRD * 2;   // 73728 B
    cudaFuncSetAttribute(attn_kernel, cudaFuncAttributeMaxDynamicSharedMemorySize, asmem);
    attn_kernel<<<dim3(Ss / 128, Hh, Bb), 128, asmem>>>(out);
}

// round 14
// speedup vs baseline: 1.1184x; 1.1184x over previous
#include <cuda_runtime.h>
#include <cuda_fp16.h>
#include <cstdint>

#define Bb 4
#define Ss 2048
#define Ee 1024
#define Hh 16
#define Dd 64
#define STRD 72   // fp16 smem row stride: 144B = 9*16B -> conflict-free ldmatrix phases

// fp16 copies of inputs (prep kernel), packed fp16x2 words
__device__ uint32_t g_Xq[(size_t)Bb * Ss * Ee / 2];
__device__ uint32_t g_Xh[(size_t)Bb * Ss * Ee / 2];
__device__ uint32_t g_Wq16[(size_t)Hh * Dd * Ee / 2];
__device__ uint32_t g_Wk16[(size_t)Hh * Dd * Ee / 2];
__device__ uint32_t g_Wv16[(size_t)Hh * Dd * Ee / 2];
// bit-packed mask: word w covers cols [w*64, w*64+64) of one (b, s) row
__device__ unsigned long long g_pm64[(size_t)Bb * Ss * Ss / 64];
// projected Q/K/V, fp16 packed, (B,H,S,D)
#define NWORDS (size_t)(Bb * Hh * Ss * Dd / 2)
__device__ uint32_t g_Qh[NWORDS];
__device__ uint32_t g_Kh[NWORDS];
__device__ uint32_t g_Vh[NWORDS];

// ---------------- helpers ----------------
__device__ __forceinline__ uint32_t pack_f16x2(float lo, float hi) {
    __half2 h = __floats2half2_rn(lo, hi);
    return *(uint32_t*)&h;
}
__device__ __forceinline__ float ex2f(float x) {
    float r; asm("ex2.approx.f32 %0, %1;" : "=f"(r) : "f"(x)); return r;
}
__device__ __forceinline__ uint32_t ex2h2(uint32_t x) {
    uint32_t r; asm("ex2.approx.f16x2 %0, %1;" : "=r"(r) : "r"(x)); return r;
}
__device__ __forceinline__ uint32_t hmin2u(uint32_t a, uint32_t b) {
    __half2 r = __hmin2(*(__half2*)&a, *(__half2*)&b);
    return *(uint32_t*)&r;
}
__device__ __forceinline__ uint32_t hmax2u(uint32_t a, uint32_t b) {
    __half2 r = __hmax2(*(__half2*)&a, *(__half2*)&b);
    return *(uint32_t*)&r;
}
__device__ __forceinline__ uint32_t hfma2u(uint32_t a, uint32_t b, uint32_t c) {
    __half2 r = __hfma2(*(__half2*)&a, *(__half2*)&b, *(__half2*)&c);
    return *(uint32_t*)&r;
}
// f32-accum fp16 MMA
__device__ __forceinline__ void mma16816(float c[4], const uint32_t a[4], uint32_t b0, uint32_t b1) {
    asm volatile(
        "mma.sync.aligned.m16n8k16.row.col.f32.f16.f16.f32 "
        "{%0,%1,%2,%3},{%4,%5,%6,%7},{%8,%9},{%0,%1,%2,%3};\n"
        : "+f"(c[0]), "+f"(c[1]), "+f"(c[2]), "+f"(c[3])
        : "r"(a[0]), "r"(a[1]), "r"(a[2]), "r"(a[3]), "r"(b0), "r"(b1));
}
// f16-accum fp16 MMA (full rate)
__device__ __forceinline__ void mma16816h(uint32_t c[2], const uint32_t a[4], uint32_t b0, uint32_t b1) {
    asm volatile(
        "mma.sync.aligned.m16n8k16.row.col.f16.f16.f16.f16 "
        "{%0,%1},{%2,%3,%4,%5},{%6,%7},{%0,%1};\n"
        : "+r"(c[0]), "+r"(c[1])
        : "r"(a[0]), "r"(a[1]), "r"(a[2]), "r"(a[3]), "r"(b0), "r"(b1));
}
__device__ __forceinline__ void ldmA(const unsigned short* t, int row0, int k0, uint32_t r[4]) {
    int lane = threadIdx.x & 31;
    int rr = row0 + (lane & 7) + 8 * ((lane >> 3) & 1);
    int cc = k0 + 8 * (lane >> 4);
    uint32_t a = (uint32_t)__cvta_generic_to_shared(t + rr * STRD + cc);
    asm volatile("ldmatrix.sync.aligned.m8n8.x4.shared.b16 {%0,%1,%2,%3},[%4];"
                 : "=r"(r[0]), "=r"(r[1]), "=r"(r[2]), "=r"(r[3]) : "r"(a));
}
__device__ __forceinline__ void ldmB(const unsigned short* t, int n0, int k0, uint32_t r[4]) {
    int lane = threadIdx.x & 31;
    int rr = n0 + (lane & 7) + 8 * (lane >> 4);
    int cc = k0 + 8 * ((lane >> 3) & 1);
    uint32_t a = (uint32_t)__cvta_generic_to_shared(t + rr * STRD + cc);
    asm volatile("ldmatrix.sync.aligned.m8n8.x4.shared.b16 {%0,%1,%2,%3},[%4];"
                 : "=r"(r[0]), "=r"(r[1]), "=r"(r[2]), "=r"(r[3]) : "r"(a));
}
__device__ __forceinline__ void ldmBT(const unsigned short* t, int kk0, int d0, uint32_t r[4]) {
    int lane = threadIdx.x & 31;
    int rr = kk0 + (lane & 7) + 8 * ((lane >> 3) & 1);
    int cc = d0 + 8 * (lane >> 4);
    uint32_t a = (uint32_t)__cvta_generic_to_shared(t + rr * STRD + cc);
    asm volatile("ldmatrix.sync.aligned.m8n8.x4.trans.shared.b16 {%0,%1,%2,%3},[%4];"
                 : "=r"(r[0]), "=r"(r[1]), "=r"(r[2]), "=r"(r[3]) : "r"(a));
}
__device__ __forceinline__ void cp16(void* smem_dst, const void* gsrc) {
    uint32_t s = (uint32_t)__cvta_generic_to_shared(smem_dst);
    asm volatile("cp.async.ca.shared.global [%0], [%1], 16;" :: "r"(s), "l"(gsrc));
}

// ---------------------------------------------------------------------------
// Prep: fp32 -> fp16 packed copies of q, hx, Wq, Wk, Wv
// ---------------------------------------------------------------------------
__global__ __launch_bounds__(256) void prep_f16(const float* __restrict__ q,
                                                const float* __restrict__ hx,
                                                const float* __restrict__ Wq,
                                                const float* __restrict__ Wk,
                                                const float* __restrict__ Wv) {
    const int z = blockIdx.y;
    const float* src = (z == 0) ? q : (z == 1) ? hx : (z == 2) ? Wq : (z == 3) ? Wk : Wv;
    uint32_t* dst = (z == 0) ? g_Xq : (z == 1) ? g_Xh : (z == 2) ? g_Wq16 : (z == 3) ? g_Wk16 : g_Wv16;
    size_t n = (z < 2) ? ((size_t)Bb * Ss * Ee / 2) : ((size_t)Hh * Dd * Ee / 2);
    size_t stride = (size_t)gridDim.x * blockDim.x;
    for (size_t i = (size_t)blockIdx.x * blockDim.x + threadIdx.x; i < n; i += stride) {
        float2 v = ((const float2*)src)[i];
        dst[i] = pack_f16x2(v.x, v.y);
    }
}

// mask (int32, nonzero = disallowed) -> bitmask, 64 cols per uint64
__global__ __launch_bounds__(256) void prep_mask(const int* __restrict__ mask) {
    int lane = threadIdx.x & 31;
    size_t gw = ((size_t)blockIdx.x * blockDim.x + threadIdx.x) >> 5;
    size_t nw = ((size_t)gridDim.x * blockDim.x) >> 5;
    const size_t NW = (size_t)Bb * Ss * Ss / 64;
    for (size_t w = gw; w < NW; w += nw) {
        const int* p = mask + w * 64;
        uint32_t b0 = __ballot_sync(0xffffffffu, p[lane] != 0);
        uint32_t b1 = __ballot_sync(0xffffffffu, p[lane + 32] != 0);
        if (lane == 0)
            g_pm64[w] = (unsigned long long)b0 | ((unsigned long long)b1 << 32);
    }
}

// ---------------------------------------------------------------------------
// Projections: C = X @ W^T (fp16 in, fp16 packed out, (B,H,S,D)).
// BM=128, BN=128, BK=64. 128 threads, 4 warps as 2(m64) x 2(n64).
// 2-stage cp.async, single barrier per chunk. 2 CTAs/SM (round-11 proven).
// ---------------------------------------------------------------------------
__global__ __launch_bounds__(128, 2) void proj_kernel() {
    extern __shared__ unsigned short sm16[];
    const int z = blockIdx.z;
    const uint32_t* X = (z == 0) ? g_Xq : g_Xh;
    const uint32_t* W = (z == 0) ? g_Wq16 : (z == 1) ? g_Wk16 : g_Wv16;
    uint32_t* dst = (z == 0) ? g_Qh : (z == 1) ? g_Kh : g_Vh;

    const int tid = threadIdx.x;
    const int wid = tid >> 5, lane = tid & 31;
    const int g = lane >> 2, t4 = lane & 3;
    const int wm = wid >> 1, wn = wid & 1;
    const int mbase = blockIdx.y * 128;
    const int nbase = blockIdx.x * 128;

#define PSTAGE(st) (sm16 + (st) * 256 * STRD)
#define PROJ_ISSUE(et, st)                                                        \
    {                                                                             \
        unsigned short* xs_ = PSTAGE(st);                                         \
        unsigned short* ws_ = PSTAGE(st) + 128 * STRD;                            \
        int ew_ = (et) * 32; /* word offset of e-chunk */                         \
        _Pragma("unroll")                                                         \
        for (int i_ = 0; i_ < 16; i_++) {                                         \
            int slot_ = i_ * 128 + tid;                                           \
            if (slot_ < 1024) {                                                   \
                int r_ = slot_ >> 3, c_ = slot_ & 7;                              \
                cp16(xs_ + r_ * STRD + c_ * 8,                                    \
                     X + (size_t)(mbase + r_) * 512 + ew_ + c_ * 4);              \
            } else {                                                              \
                int s2_ = slot_ - 1024;                                           \
                int r_ = s2_ >> 3, c_ = s2_ & 7;                                  \
                cp16(ws_ + r_ * STRD + c_ * 8,                                    \
                     W + (size_t)(nbase + r_) * 512 + ew_ + c_ * 4);              \
            }                                                                     \
        }                                                                         \
        asm volatile("cp.async.commit_group;");                                   \
    }

    float c[4][8][4] = {};
    PROJ_ISSUE(0, 0);
    asm volatile("cp.async.wait_group 0;");
    __syncthreads();                          // stage 0 ready, all warps present

    for (int et = 0; et < 16; et++) {
        if (et + 1 < 16) PROJ_ISSUE(et + 1, (et + 1) & 1);

        const unsigned short* Xs = PSTAGE(et & 1);
        const unsigned short* Ws = PSTAGE(et & 1) + 128 * STRD;

#pragma unroll
        for (int ks = 0; ks < 4; ks++) {
            uint32_t ax[4][4], bw[4][4];
#pragma unroll
            for (int mt = 0; mt < 4; mt++) ldmA(Xs, wm * 64 + mt * 16, ks * 16, ax[mt]);
#pragma unroll
            for (int nt2 = 0; nt2 < 4; nt2++) ldmB(Ws, wn * 64 + nt2 * 16, ks * 16, bw[nt2]);
#pragma unroll
            for (int mt = 0; mt < 4; mt++)
#pragma unroll
                for (int nt2 = 0; nt2 < 4; nt2++) {
                    mma16816(c[mt][2 * nt2],     ax[mt], bw[nt2][0], bw[nt2][1]);
                    mma16816(c[mt][2 * nt2 + 1], ax[mt], bw[nt2][2], bw[nt2][3]);
                }
        }

        if (et + 1 < 16) {
            asm volatile("cp.async.wait_group 0;");
            __syncthreads();
        }
    }

    // epilogue: each warp's n64 block == one head
    const int h = blockIdx.x * 2 + wn;
#pragma unroll
    for (int mt = 0; mt < 4; mt++) {
        int m0 = mbase + wm * 64 + mt * 16 + g;
        int b = m0 >> 11, s0 = m0 & 2047;
        size_t base0 = (((size_t)b * Hh + h) * Ss + s0) * (Dd / 2);
        size_t base1 = base0 + 8 * (Dd / 2);
#pragma unroll
        for (int nt = 0; nt < 8; nt++) {
            int dw = nt * 4 + t4;   // d/2
            dst[base0 + dw] = pack_f16x2(c[mt][nt][0], c[mt][nt][1]);
            dst[base1 + dw] = pack_f16x2(c[mt][nt][2], c[mt][nt][3]);
        }
    }
}

// ---------------------------------------------------------------------------
// Flash attention. CTA = 128 q-rows x (h, b); 4 warps, warp owns 32 q-rows.
// QK^T in f16 accumulators; mask = hmin2 vs ±inf; exp fused f16x2;
// l via ones-MMA with CONSTANT B-fragment (bit-identical to ldmatrix of an
// all-ones region; verified rel_err unchanged); 4-stage cp.async, single
// barrier; rescale-skip vote; packed hmax2 shuffles; persistent nm2 bias.
// ---------------------------------------------------------------------------
#define SCLOG2 0.18033688011112042f  // 0.125 * log2(e)
#define MRINIT -30.0f
#define NKT (Ss / 64)                 // 32 k-tiles
#define ASTAGE(st) (sm16 + (st) * 128 * STRD)   // K at +0 (64 rows), V at +64*STRD

__global__ __launch_bounds__(128, 2) void attn_kernel(float* __restrict__ out) {
    extern __shared__ unsigned short sm16[];

    const int qt = blockIdx.x, h = blockIdx.y, b = blockIdx.z;
    const int tid = threadIdx.x;
    const int wid = tid >> 5, lane = tid & 31;
    const int g = lane >> 2, t4 = lane & 3;

    const size_t bh_base = ((size_t)b * Hh + h) * Ss;
    const uint32_t* Kg = g_Kh + bh_base * (Dd / 2);
    const uint32_t* Vg = g_Vh + bh_base * (Dd / 2);

    {
        const uint32_t* Qg = g_Qh + (bh_base + qt * 128) * (Dd / 2);
#pragma unroll
        for (int i = 0; i < 8; i++) {
            int slot = i * 128 + tid;
            int r = slot >> 3, c = slot & 7;
            *(int4*)(sm16 + r * STRD + c * 8) = *(const int4*)&Qg[r * 32 + c * 4];
        }
    }
    __syncthreads();
    uint32_t aq[2][4][4];
#pragma unroll
    for (int mh = 0; mh < 2; mh++)
#pragma unroll
        for (int ks = 0; ks < 4; ks++)
            ldmA(sm16, wid * 32 + mh * 16, ks * 16, aq[mh][ks]);
    __syncthreads();   // everyone done reading Q before pipeline overwrites

#define ATTN_ISSUE(kt, st)                                                        \
    {                                                                             \
        const uint32_t* ks_ = Kg + (size_t)(kt) * 64 * 32;                        \
        const uint32_t* vs_ = Vg + (size_t)(kt) * 64 * 32;                        \
        unsigned short* kb_ = ASTAGE(st);                                         \
        unsigned short* vb_ = ASTAGE(st) + 64 * STRD;                             \
        _Pragma("unroll")                                                         \
        for (int i_ = 0; i_ < 8; i_++) {                                          \
            int slot_ = i_ * 128 + tid;                                           \
            int r_ = (slot_ >> 3) & 63, c_ = slot_ & 7;                           \
            if (slot_ < 512) cp16(kb_ + r_ * STRD + c_ * 8, ks_ + r_ * 32 + c_ * 4); \
            else             cp16(vb_ + r_ * STRD + c_ * 8, vs_ + r_ * 32 + c_ * 4); \
        }                                                                         \
        asm volatile("cp.async.commit_group;");                                   \
    }

    ATTN_ISSUE(0, 0);
    ATTN_ISSUE(1, 1);
    ATTN_ISSUE(2, 2);

    float o[2][8][4] = {};
    float lacc[2][4] = {};
    float mr[4] = {MRINIT, MRINIT, MRINIT, MRINIT};
    uint32_t nm2[4];
#pragma unroll
    for (int rgi = 0; rgi < 4; rgi++)
        nm2[rgi] = pack_f16x2(-MRINIT * SCLOG2, -MRINIT * SCLOG2);

    const int r0 = qt * 128 + wid * 32 + g;
    const unsigned long long* pmr = g_pm64 + ((size_t)b * Ss + r0) * (Ss / 64);

    for (int kt = 0; kt < NKT; kt++) {
        unsigned long long mA = pmr[kt];
        unsigned long long mB = pmr[kt + 8 * (Ss / 64)];
        unsigned long long mC = pmr[kt + 16 * (Ss / 64)];
        unsigned long long mD = pmr[kt + 24 * (Ss / 64)];

        asm volatile("cp.async.wait_group 2;");
        __syncthreads();
        if (kt + 3 < NKT) { ATTN_ISSUE(kt + 3, (kt + 3) & 3); }
        else { asm volatile("cp.async.commit_group;"); }

        const unsigned short* Kt = ASTAGE(kt & 3);
        const unsigned short* Vt = ASTAGE(kt & 3) + 64 * STRD;

        uint32_t s2[2][8][2];
#pragma unroll
        for (int mh = 0; mh < 2; mh++)
#pragma unroll
            for (int nt = 0; nt < 8; nt++) { s2[mh][nt][0] = 0u; s2[mh][nt][1] = 0u; }
#pragma unroll
        for (int ks = 0; ks < 4; ks++) {
            uint32_t bk[4][4];
#pragma unroll
            for (int nt2 = 0; nt2 < 4; nt2++) ldmB(Kt, nt2 * 16, ks * 16, bk[nt2]);
#pragma unroll
            for (int mh = 0; mh < 2; mh++)
#pragma unroll
                for (int nt2 = 0; nt2 < 4; nt2++) {
                    mma16816h(s2[mh][2 * nt2],     aq[mh][ks], bk[nt2][0], bk[nt2][1]);
                    mma16816h(s2[mh][2 * nt2 + 1], aq[mh][ks], bk[nt2][2], bk[nt2][3]);
                }
        }

#pragma unroll
        for (int nt = 0; nt < 8; nt++) {
            int sh = nt * 8 + 2 * t4;
            uint32_t a2 = (uint32_t)(mA >> sh) & 3u;
            uint32_t b2 = (uint32_t)(mB >> sh) & 3u;
            uint32_t c2 = (uint32_t)(mC >> sh) & 3u;
            uint32_t d2 = (uint32_t)(mD >> sh) & 3u;
            s2[0][nt][0] = hmin2u(s2[0][nt][0], 0x7C007C00u | ((a2 & 1) << 15) | ((a2 & 2) << 30));
            s2[0][nt][1] = hmin2u(s2[0][nt][1], 0x7C007C00u | ((b2 & 1) << 15) | ((b2 & 2) << 30));
            s2[1][nt][0] = hmin2u(s2[1][nt][0], 0x7C007C00u | ((c2 & 1) << 15) | ((c2 & 2) << 30));
            s2[1][nt][1] = hmin2u(s2[1][nt][1], 0x7C007C00u | ((d2 & 1) << 15) | ((d2 & 2) << 30));
        }

        // ---- row max: hmax2 tree, then pairwise-packed quad reduction ----
        uint32_t m2[4] = {0xFC00FC00u, 0xFC00FC00u, 0xFC00FC00u, 0xFC00FC00u};
#pragma unroll
        for (int nt = 0; nt < 8; nt++) {
            m2[0] = hmax2u(m2[0], s2[0][nt][0]);
            m2[1] = hmax2u(m2[1], s2[0][nt][1]);
            m2[2] = hmax2u(m2[2], s2[1][nt][0]);
            m2[3] = hmax2u(m2[3], s2[1][nt][1]);
        }
        __half2 h01 = __halves2half2(
            __hmax(__low2half(*(__half2*)&m2[0]), __high2half(*(__half2*)&m2[0])),
            __hmax(__low2half(*(__half2*)&m2[1]), __high2half(*(__half2*)&m2[1])));
        __half2 h23 = __halves2half2(
            __hmax(__low2half(*(__half2*)&m2[2]), __high2half(*(__half2*)&m2[2])),
            __hmax(__low2half(*(__half2*)&m2[3]), __high2half(*(__half2*)&m2[3])));
        uint32_t p01 = *(uint32_t*)&h01, p23 = *(uint32_t*)&h23;
        p01 = hmax2u(p01, __shfl_xor_sync(0xffffffffu, p01, 1));
        p01 = hmax2u(p01, __shfl_xor_sync(0xffffffffu, p01, 2));
        p23 = hmax2u(p23, __shfl_xor_sync(0xffffffffu, p23, 1));
        p23 = hmax2u(p23, __shfl_xor_sync(0xffffffffu, p23, 2));
        float2 f01 = __half22float2(*(__half2*)&p01);
        float2 f23 = __half22float2(*(__half2*)&p23);
        float mn[4];
        mn[0] = fmaxf(mr[0], f01.x);
        mn[1] = fmaxf(mr[1], f01.y);
        mn[2] = fmaxf(mr[2], f23.x);
        mn[3] = fmaxf(mr[3], f23.y);
        bool same = (mn[0] == mr[0]) && (mn[1] == mr[1]) &&
                    (mn[2] == mr[2]) && (mn[3] == mr[3]);
        if (!__all_sync(0xffffffffu, same)) {
            float corr[4];
#pragma unroll
            for (int rgi = 0; rgi < 4; rgi++) {
                corr[rgi] = ex2f((mr[rgi] - mn[rgi]) * SCLOG2);
                mr[rgi] = mn[rgi];
                float nmv = -mr[rgi] * SCLOG2;
                nm2[rgi] = pack_f16x2(nmv, nmv);
            }
#pragma unroll
            for (int nd = 0; nd < 8; nd++) {
                o[0][nd][0] *= corr[0]; o[0][nd][1] *= corr[0];
                o[0][nd][2] *= corr[1]; o[0][nd][3] *= corr[1];
                o[1][nd][0] *= corr[2]; o[1][nd][1] *= corr[2];
                o[1][nd][2] *= corr[3]; o[1][nd][3] *= corr[3];
            }
            lacc[0][0] *= corr[0]; lacc[0][1] *= corr[0];
            lacc[0][2] *= corr[1]; lacc[0][3] *= corr[1];
            lacc[1][0] *= corr[2]; lacc[1][1] *= corr[2];
            lacc[1][2] *= corr[3]; lacc[1][3] *= corr[3];
        }

        const uint32_t sc2 = 0x31C631C6u;   // half2(0.18033688)
#pragma unroll
        for (int mh = 0; mh < 2; mh++)
#pragma unroll
            for (int nt = 0; nt < 8; nt++) {
                s2[mh][nt][0] = ex2h2(hfma2u(s2[mh][nt][0], sc2, nm2[2 * mh]));
                s2[mh][nt][1] = ex2h2(hfma2u(s2[mh][nt][1], sc2, nm2[2 * mh + 1]));
            }

        // ---- O += P V ; l += P @ ones (constant ones B-fragment) ----
        const uint32_t ONE2 = 0x3C003C00u;
#pragma unroll
        for (int ks2 = 0; ks2 < 4; ks2++) {
            uint32_t bv[4][4];
#pragma unroll
            for (int d2 = 0; d2 < 4; d2++) ldmBT(Vt, ks2 * 16, d2 * 16, bv[d2]);
#pragma unroll
            for (int mh = 0; mh < 2; mh++) {
                const uint32_t pa[4] = {s2[mh][2 * ks2][0], s2[mh][2 * ks2][1],
                                        s2[mh][2 * ks2 + 1][0], s2[mh][2 * ks2 + 1][1]};
#pragma unroll
                for (int d2 = 0; d2 < 4; d2++) {
                    mma16816(o[mh][2 * d2],     pa, bv[d2][0], bv[d2][1]);
                    mma16816(o[mh][2 * d2 + 1], pa, bv[d2][2], bv[d2][3]);
                }
                mma16816(lacc[mh], pa, ONE2, ONE2);
            }
        }
    }

#pragma unroll
    for (int mh = 0; mh < 2; mh++) {
        float invA = 1.f / fmaxf(lacc[mh][0], 1e-30f);
        float invB = 1.f / fmaxf(lacc[mh][2], 1e-30f);
        int rA = r0 + 16 * mh, rB = rA + 8;
        float* oA = out + ((size_t)b * Ss + rA) * (Hh * Dd) + h * Dd;
        float* oB = out + ((size_t)b * Ss + rB) * (Hh * Dd) + h * Dd;
#pragma unroll
        for (int nd = 0; nd < 8; nd++) {
            int d = nd * 8 + 2 * t4;
            *(float2*)&oA[d] = make_float2(o[mh][nd][0] * invA, o[mh][nd][1] * invA);
            *(float2*)&oB[d] = make_float2(o[mh][nd][2] * invB, o[mh][nd][3] * invB);
        }
    }
}

// ---------------------------------------------------------------------------
extern "C" void kernel_launch(void* const* d_in, const int* in_sizes, int n_in,
                              void* d_out, int out_size) {
    const float* q  = (const float*)d_in[0];
    const float* hx = (const float*)d_in[1];
    const int* mask = (const int*)d_in[2];
    const float* Wq = (const float*)d_in[3];
    const float* Wk = (const float*)d_in[4];
    const float* Wv = (const float*)d_in[5];
    float* out = (float*)d_out;

    prep_f16<<<dim3(2048, 5), 256>>>(q, hx, Wq, Wk, Wv);
    prep_mask<<<2048, 256>>>(mask);

    const int psmem = 2 * 256 * STRD * 2;   // 73728 B (2 stages)
    cudaFuncSetAttribute(proj_kernel, cudaFuncAttributeMaxDynamicSharedMemorySize, psmem);
    proj_kernel<<<dim3(Hh * Dd / 128, Bb * Ss / 128, 3), 128, psmem>>>();

    const int asmem = 4 * 128 * STRD * 2;   // 73728 B
    cudaFuncSetAttribute(attn_kernel, cudaFuncAttributeMaxDynamicSharedMemorySize, asmem);
    attn_kernel<<<dim3(Ss / 128, Hh, Bb), 128, asmem>>>(out);
}